// round 2
// baseline (speedup 1.0000x reference)
#include <cuda_runtime.h>
#include <math.h>
#include <stdint.h>

#define DD 1024
#define NMAX 768
#define EMAX 24576

// ---------------- scratch (__device__ globals; no allocations allowed) ------
__device__ __align__(16) float g_P [NMAX*DD], g_Q [NMAX*DD];
__device__ __align__(16) float g_A1[NMAX*DD], g_A2[NMAX*DD], g_B1[NMAX*DD], g_B2[NMAX*DD];
__device__ __align__(16) float g_Cs[NMAX*DD], g_Co[NMAX*DD], g_Ds[NMAX*DD], g_Do[NMAX*DD];
__device__ __align__(16) float g_ctx[NMAX*DD], g_U[NMAX*DD];
__device__ __align__(16) float g_M [DD*DD], g_M2[DD*DD], g_M4[DD*DD];
__device__ __align__(16) float g_G [NMAX*NMAX], g_T[NMAX*NMAX];
__device__ __align__(16) float g_quad8[(size_t)EMAX*8];
__device__ float g_logits[EMAX], g_es[EMAX], g_eo[EMAX];
__device__ float g_c1[NMAX], g_c2[NMAX], g_Ss[NMAX], g_So[NMAX];
__device__ float g_a0[DD], g_b0[DD];
__device__ unsigned g_ms[NMAX], g_mo[NMAX];
__device__ int g_flag[NMAX];

// ---------------- fp32 tiled GEMM: C[M,N] (+)= A[M,K] @ op(B) ---------------
// BN=128 fixed, BK=16, TN=8, 256 threads. TM = BM/16.
// TB=false: B is K x N (ldb). TB=true: B is N x K (ldb), C = A @ B^T.
// Requires: M % BM == 0, N % 128 == 0, K % 16 == 0, 16B-aligned rows.
template<int BM, int TM, bool TB, bool ACC>
__global__ __launch_bounds__(256) void sgemm_k(
    const float* __restrict__ A, const float* __restrict__ B, float* __restrict__ C,
    int K, int lda, int ldb, int ldc)
{
    __shared__ float As[16][BM];
    __shared__ float Bs[16][128];
    const int tid = threadIdx.x;
    const int bm = blockIdx.y * BM;
    const int bn = blockIdx.x * 128;
    const int ty = tid >> 4, tx = tid & 15;

    float acc[TM][8];
#pragma unroll
    for (int i = 0; i < TM; i++)
#pragma unroll
        for (int j = 0; j < 8; j++) acc[i][j] = 0.f;

    for (int k0 = 0; k0 < K; k0 += 16) {
        // A tile: BM rows x 16 k, stored transposed As[k][m]
#pragma unroll
        for (int l = 0; l < BM / 64; l++) {
            int idx = tid + l * 256;
            int row = idx >> 2, kq = (idx & 3) << 2;
            float4 v = *reinterpret_cast<const float4*>(&A[(size_t)(bm + row) * lda + k0 + kq]);
            As[kq + 0][row] = v.x; As[kq + 1][row] = v.y;
            As[kq + 2][row] = v.z; As[kq + 3][row] = v.w;
        }
        if (!TB) {
#pragma unroll
            for (int l = 0; l < 2; l++) {
                int idx = tid + l * 256;
                int kk = idx >> 5, nq = (idx & 31) << 2;
                *reinterpret_cast<float4*>(&Bs[kk][nq]) =
                    *reinterpret_cast<const float4*>(&B[(size_t)(k0 + kk) * ldb + bn + nq]);
            }
        } else {
#pragma unroll
            for (int l = 0; l < 2; l++) {
                int idx = tid + l * 256;
                int row = idx >> 2, kq = (idx & 3) << 2;
                float4 v = *reinterpret_cast<const float4*>(&B[(size_t)(bn + row) * ldb + k0 + kq]);
                Bs[kq + 0][row] = v.x; Bs[kq + 1][row] = v.y;
                Bs[kq + 2][row] = v.z; Bs[kq + 3][row] = v.w;
            }
        }
        __syncthreads();
#pragma unroll
        for (int kk = 0; kk < 16; kk++) {
            float a[TM], b[8];
#pragma unroll
            for (int q = 0; q < TM / 4; q++)
                *reinterpret_cast<float4*>(&a[q * 4]) =
                    *reinterpret_cast<const float4*>(&As[kk][ty * TM + q * 4]);
            *reinterpret_cast<float4*>(&b[0]) = *reinterpret_cast<const float4*>(&Bs[kk][tx * 8]);
            *reinterpret_cast<float4*>(&b[4]) = *reinterpret_cast<const float4*>(&Bs[kk][tx * 8 + 4]);
#pragma unroll
            for (int i = 0; i < TM; i++)
#pragma unroll
                for (int j = 0; j < 8; j++)
                    acc[i][j] += a[i] * b[j];
        }
        __syncthreads();
    }
#pragma unroll
    for (int i = 0; i < TM; i++) {
        float* cp = C + (size_t)(bm + ty * TM + i) * ldc + bn + tx * 8;
        float4 r0 = make_float4(acc[i][0], acc[i][1], acc[i][2], acc[i][3]);
        float4 r1 = make_float4(acc[i][4], acc[i][5], acc[i][6], acc[i][7]);
        if (ACC) {
            float4 c0 = *reinterpret_cast<const float4*>(cp);
            float4 c1v = *reinterpret_cast<const float4*>(cp + 4);
            r0.x += c0.x; r0.y += c0.y; r0.z += c0.z; r0.w += c0.w;
            r1.x += c1v.x; r1.y += c1v.y; r1.z += c1v.z; r1.w += c1v.w;
        }
        *reinterpret_cast<float4*>(cp) = r0;
        *reinterpret_cast<float4*>(cp + 4) = r1;
    }
}

// ---------------- fused quadratic term: q8[e][bx] = sum_{j in colblk} rvf[e]*(rvf@M4)[e,j]
// Identical mainloop to sgemm<128,8,false>, but the epilogue dots each output row
// with the matching rvf columns and stores one partial per column-block (no atomics).
__global__ __launch_bounds__(256) void k_quad(
    const float* __restrict__ A /*rvf*/, const float* __restrict__ B /*M4*/)
{
    __shared__ float As[16][128];
    __shared__ float Bs[16][128];
    __shared__ float red[128][17];
    const int tid = threadIdx.x;
    const int bm = blockIdx.y * 128;
    const int bn = blockIdx.x * 128;
    const int ty = tid >> 4, tx = tid & 15;

    float acc[8][8];
#pragma unroll
    for (int i = 0; i < 8; i++)
#pragma unroll
        for (int j = 0; j < 8; j++) acc[i][j] = 0.f;

    for (int k0 = 0; k0 < DD; k0 += 16) {
#pragma unroll
        for (int l = 0; l < 2; l++) {
            int idx = tid + l * 256;
            int row = idx >> 2, kq = (idx & 3) << 2;
            float4 v = *reinterpret_cast<const float4*>(&A[(size_t)(bm + row) * DD + k0 + kq]);
            As[kq + 0][row] = v.x; As[kq + 1][row] = v.y;
            As[kq + 2][row] = v.z; As[kq + 3][row] = v.w;
        }
#pragma unroll
        for (int l = 0; l < 2; l++) {
            int idx = tid + l * 256;
            int kk = idx >> 5, nq = (idx & 31) << 2;
            *reinterpret_cast<float4*>(&Bs[kk][nq]) =
                *reinterpret_cast<const float4*>(&B[(size_t)(k0 + kk) * DD + bn + nq]);
        }
        __syncthreads();
#pragma unroll
        for (int kk = 0; kk < 16; kk++) {
            float a[8], b[8];
            *reinterpret_cast<float4*>(&a[0]) = *reinterpret_cast<const float4*>(&As[kk][ty * 8]);
            *reinterpret_cast<float4*>(&a[4]) = *reinterpret_cast<const float4*>(&As[kk][ty * 8 + 4]);
            *reinterpret_cast<float4*>(&b[0]) = *reinterpret_cast<const float4*>(&Bs[kk][tx * 8]);
            *reinterpret_cast<float4*>(&b[4]) = *reinterpret_cast<const float4*>(&Bs[kk][tx * 8 + 4]);
#pragma unroll
            for (int i = 0; i < 8; i++)
#pragma unroll
                for (int j = 0; j < 8; j++)
                    acc[i][j] += a[i] * b[j];
        }
        __syncthreads();
    }
    // epilogue: partial[i] = sum_j acc[i][j] * rvf[row, bn + tx*8 + j]
#pragma unroll
    for (int i = 0; i < 8; i++) {
        int row = bm + ty * 8 + i;
        float4 v0 = *reinterpret_cast<const float4*>(&A[(size_t)row * DD + bn + tx * 8]);
        float4 v1 = *reinterpret_cast<const float4*>(&A[(size_t)row * DD + bn + tx * 8 + 4]);
        float p = acc[i][0] * v0.x + acc[i][1] * v0.y + acc[i][2] * v0.z + acc[i][3] * v0.w
                + acc[i][4] * v1.x + acc[i][5] * v1.y + acc[i][6] * v1.z + acc[i][7] * v1.w;
        red[ty * 8 + i][tx] = p;
    }
    __syncthreads();
    if (tid < 128) {
        float s = 0.f;
#pragma unroll
        for (int t = 0; t < 16; t++) s += red[tid][t];
        g_quad8[(size_t)(bm + tid) * 8 + blockIdx.x] = s;
    }
}

// ---------------- small kernels --------------------------------------------
__global__ __launch_bounds__(256) void k_init(int n) {
    int i = blockIdx.x * 256 + threadIdx.x;
    if (i < n * n) g_T[i] = 0.f;
    if (i < n) { g_Ss[i] = 0.f; g_So[i] = 0.f; g_ms[i] = 0u; g_mo[i] = 0u; g_flag[i] = 0; }
}

// out[j] = sum_k brel[k]*W[k,j] + badd[j]
__global__ void k_biasvec(const float* __restrict__ brel, const float* __restrict__ W,
                          const float* __restrict__ badd, float* __restrict__ out) {
    int j = blockIdx.x * blockDim.x + threadIdx.x;
    if (j >= DD) return;
    float acc = badd[j];
    for (int k = 0; k < DD; k++) acc += brel[k] * W[(size_t)k * DD + j];
    out[j] = acc;
}

__global__ void k_addrow(int n) {
    int idx = blockIdx.x * blockDim.x + threadIdx.x;
    if (idx >= n * DD) return;
    int j = idx & (DD - 1);
    g_A1[idx] += g_a0[j];
    g_B2[idx] += g_b0[j];
}

__global__ __launch_bounds__(256) void k_rowdot(const float* __restrict__ X,
                                                const float* __restrict__ Yw,
                                                float* __restrict__ c) {
    int i = blockIdx.x;
    __shared__ float red[256];
    float acc = 0.f;
    for (int j = threadIdx.x; j < DD; j += 256)
        acc += X[(size_t)i * DD + j] * Yw[(size_t)i * DD + j];
    red[threadIdx.x] = acc; __syncthreads();
    for (int s = 128; s; s >>= 1) {
        if (threadIdx.x < s) red[threadIdx.x] += red[threadIdx.x + s];
        __syncthreads();
    }
    if (threadIdx.x == 0) c[i] = red[0];
}

__device__ __forceinline__ unsigned f2key(float x) {
    unsigned u = __float_as_uint(x);
    return u ^ ((unsigned)((int)u >> 31) | 0x80000000u);
}
__device__ __forceinline__ float key2f(unsigned k) {
    unsigned u = (k & 0x80000000u) ? (k ^ 0x80000000u) : ~k;
    return __uint_as_float(u);
}

// one warp per edge:
// logits[e] = (rvf[e].(Ds[s]+Do[o]) + quad[e] + c1[s]+c2[o]+G[s,o]) * inv_sqrt_d
__global__ __launch_bounds__(256) void k_logits(const float* __restrict__ rvf,
                                                const int* __restrict__ sbj, const int* __restrict__ obj,
                                                int e, int n, float inv_sqrt_d) {
    int warp = (blockIdx.x * blockDim.x + threadIdx.x) >> 5;
    int lane = threadIdx.x & 31;
    if (warp >= e) return;
    int s = sbj[warp], o = obj[warp];
    const float* r  = rvf  + (size_t)warp * DD;
    const float* ds = g_Ds + (size_t)s * DD;
    const float* dd = g_Do + (size_t)o * DD;
    float acc = 0.f;
    for (int j = lane; j < DD; j += 32)
        acc += r[j] * (ds[j] + dd[j]);
#pragma unroll
    for (int off = 16; off; off >>= 1) acc += __shfl_down_sync(0xffffffffu, acc, off);
    if (lane == 0) {
        float q = 0.f;
#pragma unroll
        for (int b = 0; b < 8; b++) q += g_quad8[(size_t)warp * 8 + b];
        float l = (acc + q + g_c1[s] + g_c2[o] + g_G[s * n + o]) * inv_sqrt_d;
        g_logits[warp] = l;
        g_flag[s] = 1;
        g_flag[o] = 1;
    }
}

__global__ void k_segmax(const int* __restrict__ sbj, const int* __restrict__ obj, int e) {
    int i = blockIdx.x * blockDim.x + threadIdx.x;
    if (i >= e) return;
    unsigned k = f2key(g_logits[i]);
    atomicMax(&g_ms[sbj[i]], k);
    atomicMax(&g_mo[obj[i]], k);
}

__global__ void k_expsum(const int* __restrict__ sbj, const int* __restrict__ obj, int e) {
    int i = blockIdx.x * blockDim.x + threadIdx.x;
    if (i >= e) return;
    float l = g_logits[i];
    int s = sbj[i], o = obj[i];
    float es = expf(l - key2f(g_ms[s]));
    float eo = expf(l - key2f(g_mo[o]));
    g_es[i] = es; g_eo[i] = eo;
    atomicAdd(&g_Ss[s], es);
    atomicAdd(&g_So[o], eo);
}

__global__ void k_scatterT(const int* __restrict__ sbj, const int* __restrict__ obj, int e, int n) {
    int i = blockIdx.x * blockDim.x + threadIdx.x;
    if (i >= e) return;
    int s = sbj[i], o = obj[i];
    atomicAdd(&g_T[s * n + o], g_es[i] / g_Ss[s]);
    atomicAdd(&g_T[o * n + s], g_eo[i] / g_So[o]);
}

__global__ void k_final(const float* __restrict__ visual, const float* __restrict__ bctx,
                        float* __restrict__ out, int n) {
    int idx = blockIdx.x * blockDim.x + threadIdx.x;
    if (idx >= n * DD) return;
    int i = idx >> 10;
    int j = idx & (DD - 1);
    float v = visual[idx];
    if (g_flag[i]) v += g_U[idx] + bctx[j];
    out[idx] = v;
}

// ---------------- host orchestration ---------------------------------------
// bm64: use 64-row tiles (better wave balance for M<=1024); else 128-row tiles.
static void gemm(const float* A, const float* B, float* C,
                 int M, int N, int K, int lda, int ldb, int ldc,
                 bool tb, bool acc, bool bm64) {
    if (bm64) {
        dim3 g(N / 128, M / 64);
        if (!tb && !acc) sgemm_k<64, 4, false, false><<<g, 256>>>(A, B, C, K, lda, ldb, ldc);
        else if (!tb &&  acc) sgemm_k<64, 4, false, true ><<<g, 256>>>(A, B, C, K, lda, ldb, ldc);
        else if ( tb && !acc) sgemm_k<64, 4, true,  false><<<g, 256>>>(A, B, C, K, lda, ldb, ldc);
        else                  sgemm_k<64, 4, true,  true ><<<g, 256>>>(A, B, C, K, lda, ldb, ldc);
    } else {
        dim3 g(N / 128, M / 128);
        if (!tb && !acc) sgemm_k<128, 8, false, false><<<g, 256>>>(A, B, C, K, lda, ldb, ldc);
        else if (!tb &&  acc) sgemm_k<128, 8, false, true ><<<g, 256>>>(A, B, C, K, lda, ldb, ldc);
        else if ( tb && !acc) sgemm_k<128, 8, true,  false><<<g, 256>>>(A, B, C, K, lda, ldb, ldc);
        else                  sgemm_k<128, 8, true,  true ><<<g, 256>>>(A, B, C, K, lda, ldb, ldc);
    }
}

template <typename T>
static float* symf(T& sym) { void* p = nullptr; cudaGetSymbolAddress(&p, sym); return (float*)p; }

extern "C" void kernel_launch(void* const* d_in, const int* in_sizes, int n_in,
                              void* d_out, int out_size) {
    const float* visual = (const float*)d_in[0];
    const float* rvf    = (const float*)d_in[1];
    const float* W_rel  = (const float*)d_in[2];
    const float* b_rel  = (const float*)d_in[3];
    const float* W_sbj  = (const float*)d_in[4];
    const float* b_sbj  = (const float*)d_in[5];
    const float* W_obj  = (const float*)d_in[6];
    const float* b_obj  = (const float*)d_in[7];
    const float* W_ctx  = (const float*)d_in[8];
    const float* b_ctx  = (const float*)d_in[9];
    const int*   sbj    = (const int*)  d_in[10];
    const int*   obj    = (const int*)  d_in[11];

    const int n = in_sizes[0] / DD;   // 768
    const int e = in_sizes[10];       // 24576
    float* out = (float*)d_out;

    // weight slices (row-major)
    const float* Wr_s = W_rel;
    const float* Wr_o = W_rel + (size_t)DD * DD;
    const float* Wr_r = W_rel + (size_t)2 * DD * DD;
    const float* Ws_v = W_sbj;
    const float* Ws_r = W_sbj + (size_t)DD * DD;
    const float* Wo_v = W_obj;
    const float* Wo_r = W_obj + (size_t)DD * DD;

    float* P  = symf(g_P);  float* Q  = symf(g_Q);
    float* A1 = symf(g_A1); float* A2 = symf(g_A2);
    float* B1 = symf(g_B1); float* B2 = symf(g_B2);
    float* Cs = symf(g_Cs); float* Co = symf(g_Co);
    float* Ds = symf(g_Ds); float* Do = symf(g_Do);
    float* Ct = symf(g_ctx); float* U  = symf(g_U);
    float* M  = symf(g_M);  float* M2 = symf(g_M2); float* M4 = symf(g_M4);
    float* G  = symf(g_G);  float* T  = symf(g_T);
    float* a0 = symf(g_a0); float* b0 = symf(g_b0);
    float* c1 = symf(g_c1); float* c2 = symf(g_c2);

    // zero/seed softmax & scatter scratch (must be re-done every replay)
    k_init<<<(n * n + 255) / 256, 256>>>(n);

    // ---- weight products: M4 = Wr_r @ (Ws_r @ Wo_r^T) @ Wr_r^T
    gemm(Ws_r, Wo_r, M,  DD, DD, DD, DD, DD, DD, true,  false, true);
    gemm(Wr_r, M,    M2, DD, DD, DD, DD, DD, DD, false, false, true);
    gemm(M2,   Wr_r, M4, DD, DD, DD, DD, DD, DD, true,  false, true);

    // ---- node-side matrices
    gemm(visual, Wr_s, P,  n, DD, DD, DD, DD, DD, false, false, true);
    gemm(visual, Wr_o, Q,  n, DD, DD, DD, DD, DD, false, false, true);
    gemm(visual, Ws_v, A1, n, DD, DD, DD, DD, DD, false, false, true);
    gemm(P,      Ws_r, A1, n, DD, DD, DD, DD, DD, false, true,  true);
    gemm(Q,      Ws_r, A2, n, DD, DD, DD, DD, DD, false, false, true);
    gemm(P,      Wo_r, B1, n, DD, DD, DD, DD, DD, false, false, true);
    gemm(visual, Wo_v, B2, n, DD, DD, DD, DD, DD, false, false, true);
    gemm(Q,      Wo_r, B2, n, DD, DD, DD, DD, DD, false, true,  true);

    // bias folds: a0 = b_rel@Ws_r + b_sbj ; b0 = b_rel@Wo_r + b_obj
    k_biasvec<<<(DD + 255) / 256, 256>>>(b_rel, Ws_r, b_sbj, a0);
    k_biasvec<<<(DD + 255) / 256, 256>>>(b_rel, Wo_r, b_obj, b0);
    k_addrow<<<(n * DD + 255) / 256, 256>>>(n);

    // per-node dot terms
    k_rowdot<<<n, 256>>>(A1, B1, c1);
    k_rowdot<<<n, 256>>>(A2, B2, c2);

    // linear edge-term projections: Ds = (B1 Ws_r^T + A1 Wo_r^T) Wr_r^T (sym for Do)
    gemm(B1, Ws_r, Cs, n, DD, DD, DD, DD, DD, true, false, true);
    gemm(A1, Wo_r, Cs, n, DD, DD, DD, DD, DD, true, true,  true);
    gemm(B2, Ws_r, Co, n, DD, DD, DD, DD, DD, true, false, true);
    gemm(A2, Wo_r, Co, n, DD, DD, DD, DD, DD, true, true,  true);
    gemm(Cs, Wr_r, Ds, n, DD, DD, DD, DD, DD, true, false, true);
    gemm(Co, Wr_r, Do, n, DD, DD, DD, DD, DD, true, false, true);

    // node-pair cross matrix: G = A1 B2^T + B1 A2^T  (N x N)
    gemm(A1, B2, G, n, n, DD, DD, DD, n, true, false, true);
    gemm(B1, A2, G, n, n, DD, DD, DD, n, true, true,  true);

    // ---- fused E-scale GEMM + row-dot: g_quad8[e][bx] partials of rvf.(rvf@M4)
    {
        dim3 g(8, e / 128);
        k_quad<<<g, 256>>>(rvf, M4);
    }

    // ---- edge logits, edge softmax (both segmentations), attention matrix T
    float inv_sqrt_d = 1.0f / sqrtf((float)DD);
    k_logits <<<(e * 32 + 255) / 256, 256>>>(rvf, sbj, obj, e, n, inv_sqrt_d);
    k_segmax <<<(e + 255) / 256, 256>>>(sbj, obj, e);
    k_expsum <<<(e + 255) / 256, 256>>>(sbj, obj, e);
    k_scatterT<<<(e + 255) / 256, 256>>>(sbj, obj, e, n);

    // ---- ctx = T @ vj ; U = ctx @ W_ctx ; masked update
    gemm(T,  visual, Ct, n, DD, n,  n,  DD, DD, false, false, true);
    gemm(Ct, W_ctx,  U,  n, DD, DD, DD, DD, DD, false, false, true);

    size_t vj_off = 0;
    if ((size_t)out_size == (size_t)e * DD + (size_t)n * DD) {
        vj_off = (size_t)e * DD;
        cudaMemcpyAsync(out, rvf, (size_t)e * DD * sizeof(float),
                        cudaMemcpyDeviceToDevice, 0);
    }
    k_final<<<(n * DD + 255) / 256, 256>>>(visual, b_ctx, out + vj_off, n);
}

// round 3
// speedup vs baseline: 1.3180x; 1.3180x over previous
#include <cuda_runtime.h>
#include <math.h>
#include <stdint.h>

#define DD 1024
#define NMAX 768
#define EMAX 24576

// ---------------- scratch (__device__ globals) ------------------------------
__device__ __align__(16) float g_P [NMAX*DD], g_Q [NMAX*DD];
__device__ __align__(16) float g_CAT [NMAX*2*DD];   // [A1 | B1]
__device__ __align__(16) float g_CAT2[NMAX*2*DD];   // [B2 | A2]
__device__ __align__(16) float g_Cs[NMAX*DD], g_Co[NMAX*DD], g_Ds[NMAX*DD], g_Do[NMAX*DD];
__device__ __align__(16) float g_ctx[NMAX*DD], g_Uc[NMAX*DD];
__device__ __align__(16) float g_U1[DD*DD], g_V1[DD*DD], g_M4[DD*DD];
__device__ __align__(16) float g_G [NMAX*NMAX], g_T[NMAX*NMAX];
__device__ __align__(16) float g_quad8[(size_t)EMAX*8];
__device__ float g_logits[EMAX], g_es[EMAX], g_eo[EMAX];
__device__ float g_c1[NMAX], g_c2[NMAX], g_Ss[NMAX], g_So[NMAX];
__device__ float g_a0[DD], g_b0[DD];
__device__ unsigned g_ms[NMAX], g_mo[NMAX];
__device__ int g_flag[NMAX];

// ---------------- tf32 helpers ----------------------------------------------
__device__ __forceinline__ float cvt_tf32(float x) {
    uint32_t r;
    asm("cvt.rna.tf32.f32 %0, %1;" : "=r"(r) : "f"(x));
    return __uint_as_float(r);
}
__device__ __forceinline__ float2 split_tf32(float x) {
    float hi = cvt_tf32(x);
    float lo = cvt_tf32(x - hi);
    return make_float2(hi, lo);
}
__device__ __forceinline__ void mma_tf32(float4& d,
    uint32_t a0, uint32_t a1, uint32_t a2, uint32_t a3,
    uint32_t b0, uint32_t b1)
{
    asm volatile(
        "mma.sync.aligned.m16n8k8.row.col.f32.tf32.tf32.f32 "
        "{%0,%1,%2,%3}, {%4,%5,%6,%7}, {%8,%9}, {%0,%1,%2,%3};"
        : "+f"(d.x), "+f"(d.y), "+f"(d.z), "+f"(d.w)
        : "r"(a0), "r"(a1), "r"(a2), "r"(a3), "r"(b0), "r"(b1));
}
#define FU(x) __float_as_uint(x)

// ---------------- grouped tf32x3 GEMM ---------------------------------------
// Tile 64x128xK16, 256 threads, 8 warps (2 m-warps x 4 n-warps), warp tile 32x32.
// Per op: C[M,N] (+)= A[M,K] @ op(B). TB: B is NxK (C = A @ B^T).
// Ksplit>0: for k >= Ksplit the B operand switches to B2 (k rebased).
struct GOp {
    const float* A; const float* B; const float* B2; float* C;
    int K, Ksplit, lda, ldb, ldc;
    int ntiles, blkStart;
    int tb, acc;
};
struct GOps { GOp op[6]; int n; };

__global__ __launch_bounds__(256) void gg_k(GOps ops) {
    int oi = 0;
#pragma unroll
    for (int q = 1; q < 6; q++)
        if (q < ops.n && (int)blockIdx.x >= ops.op[q].blkStart) oi = q;
    const GOp o = ops.op[oi];
    const int local = blockIdx.x - o.blkStart;
    const int bm = (local / o.ntiles) * 64;
    const int bn = (local % o.ntiles) * 128;

    __shared__ float2 AsHL[16][64 + 8];
    __shared__ float2 BsHL[16][128 + 8];

    const int tid = threadIdx.x;
    const int lane = tid & 31, w = tid >> 5;
    const int wm = w & 1, wn = w >> 1;
    const int g = lane >> 2, t = lane & 3;

    float4 acc[2][4];
#pragma unroll
    for (int i = 0; i < 2; i++)
#pragma unroll
        for (int j = 0; j < 4; j++) acc[i][j] = make_float4(0.f, 0.f, 0.f, 0.f);

    for (int k0 = 0; k0 < o.K; k0 += 16) {
        const float* Bbase = o.B;
        int kb = k0;
        if (o.Ksplit && k0 >= o.Ksplit) { Bbase = o.B2; kb = k0 - o.Ksplit; }
        // A tile: 64 x 16
        {
            int row = tid >> 2, kq = (tid & 3) << 2;
            float4 v = *reinterpret_cast<const float4*>(&o.A[(size_t)(bm + row) * o.lda + k0 + kq]);
            AsHL[kq + 0][row] = split_tf32(v.x);
            AsHL[kq + 1][row] = split_tf32(v.y);
            AsHL[kq + 2][row] = split_tf32(v.z);
            AsHL[kq + 3][row] = split_tf32(v.w);
        }
        if (!o.tb) {
#pragma unroll
            for (int l = 0; l < 2; l++) {
                int idx = tid + l * 256;
                int kk = idx >> 5, nq = (idx & 31) << 2;
                float4 v = *reinterpret_cast<const float4*>(&Bbase[(size_t)(kb + kk) * o.ldb + bn + nq]);
                BsHL[kk][nq + 0] = split_tf32(v.x);
                BsHL[kk][nq + 1] = split_tf32(v.y);
                BsHL[kk][nq + 2] = split_tf32(v.z);
                BsHL[kk][nq + 3] = split_tf32(v.w);
            }
        } else {
#pragma unroll
            for (int l = 0; l < 2; l++) {
                int idx = tid + l * 256;
                int row = idx >> 2, kq = (idx & 3) << 2;
                float4 v = *reinterpret_cast<const float4*>(&Bbase[(size_t)(bn + row) * o.ldb + kb + kq]);
                BsHL[kq + 0][row] = split_tf32(v.x);
                BsHL[kq + 1][row] = split_tf32(v.y);
                BsHL[kq + 2][row] = split_tf32(v.z);
                BsHL[kq + 3][row] = split_tf32(v.w);
            }
        }
        __syncthreads();
#pragma unroll
        for (int ks = 0; ks < 16; ks += 8) {
            float2 a[2][4], b[4][2];
#pragma unroll
            for (int i = 0; i < 2; i++) {
                int m = wm * 32 + i * 16;
                a[i][0] = AsHL[ks + t    ][m + g];
                a[i][1] = AsHL[ks + t    ][m + g + 8];
                a[i][2] = AsHL[ks + t + 4][m + g];
                a[i][3] = AsHL[ks + t + 4][m + g + 8];
            }
#pragma unroll
            for (int j = 0; j < 4; j++) {
                int nn = wn * 32 + j * 8;
                b[j][0] = BsHL[ks + t    ][nn + g];
                b[j][1] = BsHL[ks + t + 4][nn + g];
            }
#pragma unroll
            for (int i = 0; i < 2; i++)
#pragma unroll
                for (int j = 0; j < 4; j++) {
                    mma_tf32(acc[i][j], FU(a[i][0].x), FU(a[i][1].x), FU(a[i][2].x), FU(a[i][3].x),
                             FU(b[j][0].x), FU(b[j][1].x));
                    mma_tf32(acc[i][j], FU(a[i][0].x), FU(a[i][1].x), FU(a[i][2].x), FU(a[i][3].x),
                             FU(b[j][0].y), FU(b[j][1].y));
                    mma_tf32(acc[i][j], FU(a[i][0].y), FU(a[i][1].y), FU(a[i][2].y), FU(a[i][3].y),
                             FU(b[j][0].x), FU(b[j][1].x));
                }
        }
        __syncthreads();
    }
    // epilogue
#pragma unroll
    for (int i = 0; i < 2; i++) {
        int r0 = bm + wm * 32 + i * 16 + g;
        int r1 = r0 + 8;
#pragma unroll
        for (int j = 0; j < 4; j++) {
            int c = bn + wn * 32 + j * 8 + 2 * t;
            float2 v0 = make_float2(acc[i][j].x, acc[i][j].y);
            float2 v1 = make_float2(acc[i][j].z, acc[i][j].w);
            float* p0 = o.C + (size_t)r0 * o.ldc + c;
            float* p1 = o.C + (size_t)r1 * o.ldc + c;
            if (o.acc) {
                float2 u0 = *reinterpret_cast<const float2*>(p0);
                float2 u1 = *reinterpret_cast<const float2*>(p1);
                v0.x += u0.x; v0.y += u0.y; v1.x += u1.x; v1.y += u1.y;
            }
            *reinterpret_cast<float2*>(p0) = v0;
            *reinterpret_cast<float2*>(p1) = v1;
        }
    }
}

// ---------------- fused quadratic-term GEMM (tf32x3) ------------------------
// Computes partials of diag(rvf @ M4 @ rvf^T): tile 128x128, epilogue dots each
// C element with matching rvf value, reduces per row into g_quad8[row][bx].
__global__ __launch_bounds__(256) void k_quad(
    const float* __restrict__ A /*rvf*/, const float* __restrict__ B /*M4*/)
{
    __shared__ float2 AsHL[16][128 + 8];
    __shared__ float2 BsHL[16][128 + 8];
    __shared__ float red[128];

    const int tid = threadIdx.x;
    const int lane = tid & 31, w = tid >> 5;
    const int wm = w & 1, wn = w >> 1;
    const int g = lane >> 2, t = lane & 3;
    const int bm = blockIdx.y * 128;
    const int bn = blockIdx.x * 128;

    float4 acc[4][4];
#pragma unroll
    for (int i = 0; i < 4; i++)
#pragma unroll
        for (int j = 0; j < 4; j++) acc[i][j] = make_float4(0.f, 0.f, 0.f, 0.f);

    for (int k0 = 0; k0 < DD; k0 += 16) {
#pragma unroll
        for (int l = 0; l < 2; l++) {
            int idx = tid + l * 256;
            int row = idx >> 2, kq = (idx & 3) << 2;
            float4 v = *reinterpret_cast<const float4*>(&A[(size_t)(bm + row) * DD + k0 + kq]);
            AsHL[kq + 0][row] = split_tf32(v.x);
            AsHL[kq + 1][row] = split_tf32(v.y);
            AsHL[kq + 2][row] = split_tf32(v.z);
            AsHL[kq + 3][row] = split_tf32(v.w);
        }
#pragma unroll
        for (int l = 0; l < 2; l++) {
            int idx = tid + l * 256;
            int kk = idx >> 5, nq = (idx & 31) << 2;
            float4 v = *reinterpret_cast<const float4*>(&B[(size_t)(k0 + kk) * DD + bn + nq]);
            BsHL[kk][nq + 0] = split_tf32(v.x);
            BsHL[kk][nq + 1] = split_tf32(v.y);
            BsHL[kk][nq + 2] = split_tf32(v.z);
            BsHL[kk][nq + 3] = split_tf32(v.w);
        }
        __syncthreads();
#pragma unroll
        for (int ks = 0; ks < 16; ks += 8) {
            float2 a[4][4], b[4][2];
#pragma unroll
            for (int i = 0; i < 4; i++) {
                int m = wm * 64 + i * 16;
                a[i][0] = AsHL[ks + t    ][m + g];
                a[i][1] = AsHL[ks + t    ][m + g + 8];
                a[i][2] = AsHL[ks + t + 4][m + g];
                a[i][3] = AsHL[ks + t + 4][m + g + 8];
            }
#pragma unroll
            for (int j = 0; j < 4; j++) {
                int nn = wn * 32 + j * 8;
                b[j][0] = BsHL[ks + t    ][nn + g];
                b[j][1] = BsHL[ks + t + 4][nn + g];
            }
#pragma unroll
            for (int i = 0; i < 4; i++)
#pragma unroll
                for (int j = 0; j < 4; j++) {
                    mma_tf32(acc[i][j], FU(a[i][0].x), FU(a[i][1].x), FU(a[i][2].x), FU(a[i][3].x),
                             FU(b[j][0].x), FU(b[j][1].x));
                    mma_tf32(acc[i][j], FU(a[i][0].x), FU(a[i][1].x), FU(a[i][2].x), FU(a[i][3].x),
                             FU(b[j][0].y), FU(b[j][1].y));
                    mma_tf32(acc[i][j], FU(a[i][0].y), FU(a[i][1].y), FU(a[i][2].y), FU(a[i][3].y),
                             FU(b[j][0].x), FU(b[j][1].x));
                }
        }
        __syncthreads();
    }
    if (tid < 128) red[tid] = 0.f;
    __syncthreads();
#pragma unroll
    for (int i = 0; i < 4; i++) {
        int mrow = wm * 64 + i * 16 + g;
        int r0 = bm + mrow, r1 = r0 + 8;
        float p0 = 0.f, p1 = 0.f;
#pragma unroll
        for (int j = 0; j < 4; j++) {
            int c = bn + wn * 32 + j * 8 + 2 * t;
            float2 v0 = *reinterpret_cast<const float2*>(&A[(size_t)r0 * DD + c]);
            float2 v1 = *reinterpret_cast<const float2*>(&A[(size_t)r1 * DD + c]);
            p0 += acc[i][j].x * v0.x + acc[i][j].y * v0.y;
            p1 += acc[i][j].z * v1.x + acc[i][j].w * v1.y;
        }
        atomicAdd(&red[mrow], p0);
        atomicAdd(&red[mrow + 8], p1);
    }
    __syncthreads();
    if (tid < 128)
        g_quad8[(size_t)(bm + tid) * 8 + blockIdx.x] = red[tid];
}

// ---------------- small kernels ---------------------------------------------
__global__ __launch_bounds__(256) void k_init(int n) {
    int i = blockIdx.x * 256 + threadIdx.x;
    if (i < n * n) g_T[i] = 0.f;
    if (i < n) { g_Ss[i] = 0.f; g_So[i] = 0.f; g_ms[i] = 0u; g_mo[i] = 0u; g_flag[i] = 0; }
}

__global__ void k_biasvec(const float* __restrict__ brel, const float* __restrict__ W,
                          const float* __restrict__ badd, float* __restrict__ out) {
    int j = blockIdx.x * blockDim.x + threadIdx.x;
    if (j >= DD) return;
    float acc = badd[j];
    for (int k = 0; k < DD; k++) acc += brel[k] * W[(size_t)k * DD + j];
    out[j] = acc;
}

// add a0 into A1 slot of CAT, b0 into B2 slot of CAT2
__global__ void k_addrow(int n) {
    int idx = blockIdx.x * blockDim.x + threadIdx.x;
    if (idx >= n * DD) return;
    int i = idx >> 10, j = idx & (DD - 1);
    g_CAT [(size_t)i * 2 * DD + j] += g_a0[j];
    g_CAT2[(size_t)i * 2 * DD + j] += g_b0[j];
}

// c[i] = dot(X[i][0:DD], X[i][DD:2*DD])  over a [n][2*DD] buffer
__global__ __launch_bounds__(256) void k_rowdot(const float* __restrict__ X, float* __restrict__ c) {
    int i = blockIdx.x;
    __shared__ float red[256];
    float acc = 0.f;
    const float* row = X + (size_t)i * 2 * DD;
    for (int j = threadIdx.x; j < DD; j += 256)
        acc += row[j] * row[DD + j];
    red[threadIdx.x] = acc; __syncthreads();
    for (int s = 128; s; s >>= 1) {
        if (threadIdx.x < s) red[threadIdx.x] += red[threadIdx.x + s];
        __syncthreads();
    }
    if (threadIdx.x == 0) c[i] = red[0];
}

__device__ __forceinline__ unsigned f2key(float x) {
    unsigned u = __float_as_uint(x);
    return u ^ ((unsigned)((int)u >> 31) | 0x80000000u);
}
__device__ __forceinline__ float key2f(unsigned k) {
    unsigned u = (k & 0x80000000u) ? (k ^ 0x80000000u) : ~k;
    return __uint_as_float(u);
}

__global__ __launch_bounds__(256) void k_logits(const float* __restrict__ rvf,
                                                const int* __restrict__ sbj, const int* __restrict__ obj,
                                                int e, int n, float inv_sqrt_d) {
    int warp = (blockIdx.x * blockDim.x + threadIdx.x) >> 5;
    int lane = threadIdx.x & 31;
    if (warp >= e) return;
    int s = sbj[warp], o = obj[warp];
    const float* r  = rvf  + (size_t)warp * DD;
    const float* ds = g_Ds + (size_t)s * DD;
    const float* dd = g_Do + (size_t)o * DD;
    float acc = 0.f;
    for (int j = lane; j < DD; j += 32)
        acc += r[j] * (ds[j] + dd[j]);
#pragma unroll
    for (int off = 16; off; off >>= 1) acc += __shfl_down_sync(0xffffffffu, acc, off);
    if (lane == 0) {
        float q = 0.f;
#pragma unroll
        for (int b = 0; b < 8; b++) q += g_quad8[(size_t)warp * 8 + b];
        float l = (acc + q + g_c1[s] + g_c2[o] + g_G[s * n + o]) * inv_sqrt_d;
        g_logits[warp] = l;
        g_flag[s] = 1;
        g_flag[o] = 1;
    }
}

__global__ void k_segmax(const int* __restrict__ sbj, const int* __restrict__ obj, int e) {
    int i = blockIdx.x * blockDim.x + threadIdx.x;
    if (i >= e) return;
    unsigned k = f2key(g_logits[i]);
    atomicMax(&g_ms[sbj[i]], k);
    atomicMax(&g_mo[obj[i]], k);
}

__global__ void k_expsum(const int* __restrict__ sbj, const int* __restrict__ obj, int e) {
    int i = blockIdx.x * blockDim.x + threadIdx.x;
    if (i >= e) return;
    float l = g_logits[i];
    int s = sbj[i], o = obj[i];
    float es = expf(l - key2f(g_ms[s]));
    float eo = expf(l - key2f(g_mo[o]));
    g_es[i] = es; g_eo[i] = eo;
    atomicAdd(&g_Ss[s], es);
    atomicAdd(&g_So[o], eo);
}

__global__ void k_scatterT(const int* __restrict__ sbj, const int* __restrict__ obj, int e, int n) {
    int i = blockIdx.x * blockDim.x + threadIdx.x;
    if (i >= e) return;
    int s = sbj[i], o = obj[i];
    atomicAdd(&g_T[s * n + o], g_es[i] / g_Ss[s]);
    atomicAdd(&g_T[o * n + s], g_eo[i] / g_So[o]);
}

__global__ void k_final(const float* __restrict__ visual, const float* __restrict__ bctx,
                        float* __restrict__ out, int n) {
    int idx = blockIdx.x * blockDim.x + threadIdx.x;
    if (idx >= n * DD) return;
    int i = idx >> 10;
    int j = idx & (DD - 1);
    float v = visual[idx];
    if (g_flag[i]) v += g_Uc[idx] + bctx[j];
    out[idx] = v;
}

// ---------------- host orchestration ----------------------------------------
template <typename T>
static float* symf(T& sym) { void* p = nullptr; cudaGetSymbolAddress(&p, sym); return (float*)p; }

static GOp mkop(const float* A, const float* B, const float* B2, float* C,
                int M, int N, int K, int Ksplit,
                int lda, int ldb, int ldc, bool tb, bool acc, int blkStart) {
    GOp o;
    o.A = A; o.B = B; o.B2 = B2 ? B2 : B; o.C = C;
    o.K = K; o.Ksplit = Ksplit; o.lda = lda; o.ldb = ldb; o.ldc = ldc;
    o.ntiles = N / 128; o.blkStart = blkStart;
    o.tb = tb ? 1 : 0; o.acc = acc ? 1 : 0;
    return o;
}
static int opblocks(int M, int N) { return (M / 64) * (N / 128); }

extern "C" void kernel_launch(void* const* d_in, const int* in_sizes, int n_in,
                              void* d_out, int out_size) {
    const float* visual = (const float*)d_in[0];
    const float* rvf    = (const float*)d_in[1];
    const float* W_rel  = (const float*)d_in[2];
    const float* b_rel  = (const float*)d_in[3];
    const float* W_sbj  = (const float*)d_in[4];
    const float* b_sbj  = (const float*)d_in[5];
    const float* W_obj  = (const float*)d_in[6];
    const float* b_obj  = (const float*)d_in[7];
    const float* W_ctx  = (const float*)d_in[8];
    const float* b_ctx  = (const float*)d_in[9];
    const int*   sbj    = (const int*)  d_in[10];
    const int*   obj    = (const int*)  d_in[11];

    const int n = in_sizes[0] / DD;   // 768
    const int e = in_sizes[10];       // 24576
    float* out = (float*)d_out;

    const float* Wr_s = W_rel;
    const float* Wr_o = W_rel + (size_t)DD * DD;
    const float* Wr_r = W_rel + (size_t)2 * DD * DD;
    const float* Ws_v = W_sbj;
    const float* Ws_r = W_sbj + (size_t)DD * DD;
    const float* Wo_v = W_obj;
    const float* Wo_r = W_obj + (size_t)DD * DD;

    float* P   = symf(g_P);   float* Q    = symf(g_Q);
    float* CAT = symf(g_CAT); float* CAT2 = symf(g_CAT2);
    float* A1  = CAT;         float* B1   = CAT + DD;     // ldc = 2*DD
    float* B2  = CAT2;        float* A2   = CAT2 + DD;
    float* Cs  = symf(g_Cs);  float* Co   = symf(g_Co);
    float* Ds  = symf(g_Ds);  float* Do   = symf(g_Do);
    float* Ct  = symf(g_ctx); float* Uc   = symf(g_Uc);
    float* U1  = symf(g_U1);  float* V1   = symf(g_V1);  float* M4 = symf(g_M4);
    float* G   = symf(g_G);   float* T    = symf(g_T);
    float* a0  = symf(g_a0);  float* b0   = symf(g_b0);
    float* c1  = symf(g_c1);  float* c2   = symf(g_c2);

    k_init<<<(n * n + 255) / 256, 256>>>(n);

    // ---- L1: visual@{Wr_s,Wr_o,Ws_v,Wo_v} + weight products U1,V1
    {
        GOps ops; ops.n = 6; int bs = 0;
        ops.op[0] = mkop(visual, Wr_s, 0, P,  n, DD, DD, 0, DD, DD, DD,    false, false, bs); bs += opblocks(n, DD);
        ops.op[1] = mkop(visual, Wr_o, 0, Q,  n, DD, DD, 0, DD, DD, DD,    false, false, bs); bs += opblocks(n, DD);
        ops.op[2] = mkop(visual, Ws_v, 0, A1, n, DD, DD, 0, DD, DD, 2*DD,  false, false, bs); bs += opblocks(n, DD);
        ops.op[3] = mkop(visual, Wo_v, 0, B2, n, DD, DD, 0, DD, DD, 2*DD,  false, false, bs); bs += opblocks(n, DD);
        ops.op[4] = mkop(Wr_r,   Ws_r, 0, U1, DD, DD, DD, 0, DD, DD, DD,   false, false, bs); bs += opblocks(DD, DD);
        ops.op[5] = mkop(Wr_r,   Wo_r, 0, V1, DD, DD, DD, 0, DD, DD, DD,   false, false, bs); bs += opblocks(DD, DD);
        gg_k<<<bs, 256>>>(ops);
    }
    // ---- L2: A1+=P@Ws_r, A2=Q@Ws_r, B1=P@Wo_r, B2+=Q@Wo_r, M4=U1@V1^T
    {
        GOps ops; ops.n = 5; int bs = 0;
        ops.op[0] = mkop(P, Ws_r, 0, A1, n, DD, DD, 0, DD, DD, 2*DD, false, true,  bs); bs += opblocks(n, DD);
        ops.op[1] = mkop(Q, Ws_r, 0, A2, n, DD, DD, 0, DD, DD, 2*DD, false, false, bs); bs += opblocks(n, DD);
        ops.op[2] = mkop(P, Wo_r, 0, B1, n, DD, DD, 0, DD, DD, 2*DD, false, false, bs); bs += opblocks(n, DD);
        ops.op[3] = mkop(Q, Wo_r, 0, B2, n, DD, DD, 0, DD, DD, 2*DD, false, true,  bs); bs += opblocks(n, DD);
        ops.op[4] = mkop(U1, V1,  0, M4, DD, DD, DD, 0, DD, DD, DD,  true,  false, bs); bs += opblocks(DD, DD);
        gg_k<<<bs, 256>>>(ops);
    }
    // ---- bias folds + per-node dots
    k_biasvec<<<(DD + 255) / 256, 256>>>(b_rel, Ws_r, b_sbj, a0);
    k_biasvec<<<(DD + 255) / 256, 256>>>(b_rel, Wo_r, b_obj, b0);
    k_addrow<<<(n * DD + 255) / 256, 256>>>(n);
    k_rowdot<<<n, 256>>>(CAT,  c1);   // dot(A1, B1)
    k_rowdot<<<n, 256>>>(CAT2, c2);   // dot(B2, A2) == dot(A2, B2)

    // ---- quadratic term (E-scale, fused)
    {
        dim3 g(8, e / 128);
        k_quad<<<g, 256>>>(rvf, M4);
    }
    // ---- L3: Cs, Co (K=2048 concat), G = CAT @ CAT2^T
    {
        GOps ops; ops.n = 3; int bs = 0;
        // Cs = A1@Wo_r^T + B1@Ws_r^T : CAT=[A1|B1], B switches Wo_r -> Ws_r at k=DD
        ops.op[0] = mkop(CAT,  Wo_r, Ws_r, Cs, n, DD, 2*DD, DD, 2*DD, DD,   DD,  true, false, bs); bs += opblocks(n, DD);
        // Co = B2@Ws_r^T + A2@Wo_r^T : CAT2=[B2|A2]
        ops.op[1] = mkop(CAT2, Ws_r, Wo_r, Co, n, DD, 2*DD, DD, 2*DD, DD,   DD,  true, false, bs); bs += opblocks(n, DD);
        // G = A1@B2^T + B1@A2^T = CAT @ CAT2^T (full K=2048 dot)
        ops.op[2] = mkop(CAT,  CAT2, 0,    G,  n, n,  2*DD, 0,  2*DD, 2*DD, n,   true, false, bs); bs += opblocks(n, n);
        gg_k<<<bs, 256>>>(ops);
    }
    // ---- L4: Ds = Cs@Wr_r^T, Do = Co@Wr_r^T
    {
        GOps ops; ops.n = 2; int bs = 0;
        ops.op[0] = mkop(Cs, Wr_r, 0, Ds, n, DD, DD, 0, DD, DD, DD, true, false, bs); bs += opblocks(n, DD);
        ops.op[1] = mkop(Co, Wr_r, 0, Do, n, DD, DD, 0, DD, DD, DD, true, false, bs); bs += opblocks(n, DD);
        gg_k<<<bs, 256>>>(ops);
    }
    // ---- edge logits + softmax + attention matrix
    float inv_sqrt_d = 1.0f / sqrtf((float)DD);
    k_logits  <<<(e * 32 + 255) / 256, 256>>>(rvf, sbj, obj, e, n, inv_sqrt_d);
    k_segmax  <<<(e + 255) / 256, 256>>>(sbj, obj, e);
    k_expsum  <<<(e + 255) / 256, 256>>>(sbj, obj, e);
    k_scatterT<<<(e + 255) / 256, 256>>>(sbj, obj, e, n);

    // ---- ctx = T @ visual ; U = ctx @ W_ctx
    {
        GOps ops; ops.n = 1;
        ops.op[0] = mkop(T, visual, 0, Ct, n, DD, n, 0, n, DD, DD, false, false, 0);
        gg_k<<<opblocks(n, DD), 256>>>(ops);
    }
    {
        GOps ops; ops.n = 1;
        ops.op[0] = mkop(Ct, W_ctx, 0, Uc, n, DD, DD, 0, DD, DD, DD, false, false, 0);
        gg_k<<<opblocks(n, DD), 256>>>(ops);
    }

    size_t vj_off = 0;
    if ((size_t)out_size == (size_t)e * DD + (size_t)n * DD) {
        vj_off = (size_t)e * DD;
        cudaMemcpyAsync(out, rvf, (size_t)e * DD * sizeof(float),
                        cudaMemcpyDeviceToDevice, 0);
    }
    k_final<<<(n * DD + 255) / 256, 256>>>(visual, b_ctx, out + vj_off, n);
}

// round 4
// speedup vs baseline: 1.3912x; 1.0555x over previous
#include <cuda_runtime.h>
#include <math.h>
#include <stdint.h>

#define DD 1024
#define NMAX 768
#define EMAX 24576

// ---------------- scratch (__device__ globals) ------------------------------
__device__ __align__(16) float g_P [NMAX*DD], g_Q [NMAX*DD];
__device__ __align__(16) float g_CAT [NMAX*2*DD];   // [A1 | B1]
__device__ __align__(16) float g_CAT2[NMAX*2*DD];   // [B2 | A2]
__device__ __align__(16) float g_Cs[NMAX*DD], g_Co[NMAX*DD], g_Ds[NMAX*DD], g_Do[NMAX*DD];
__device__ __align__(16) float g_ctx[NMAX*DD], g_Uc[NMAX*DD];
__device__ __align__(16) float g_U1[DD*DD], g_V1[DD*DD], g_M4[DD*DD];
__device__ __align__(16) float g_G [NMAX*NMAX], g_T[NMAX*NMAX];
__device__ __align__(16) float g_quad8[(size_t)EMAX*8];
__device__ float g_logits[EMAX], g_es[EMAX], g_eo[EMAX];
__device__ float g_c1[NMAX], g_c2[NMAX], g_Ss[NMAX], g_So[NMAX];
__device__ float g_a0[DD], g_b0[DD];
__device__ unsigned g_ms[NMAX], g_mo[NMAX];
__device__ int g_flag[NMAX];

// ---------------- tf32 helpers ----------------------------------------------
__device__ __forceinline__ float cvt_tf32(float x) {
    uint32_t r;
    asm("cvt.rna.tf32.f32 %0, %1;" : "=r"(r) : "f"(x));
    return __uint_as_float(r);
}
__device__ __forceinline__ float2 split_tf32(float x) {
    float hi = cvt_tf32(x);
    float lo = cvt_tf32(x - hi);
    return make_float2(hi, lo);
}
__device__ __forceinline__ void mma_tf32(float4& d,
    uint32_t a0, uint32_t a1, uint32_t a2, uint32_t a3,
    uint32_t b0, uint32_t b1)
{
    asm volatile(
        "mma.sync.aligned.m16n8k8.row.col.f32.tf32.tf32.f32 "
        "{%0,%1,%2,%3}, {%4,%5,%6,%7}, {%8,%9}, {%0,%1,%2,%3};"
        : "+f"(d.x), "+f"(d.y), "+f"(d.z), "+f"(d.w)
        : "r"(a0), "r"(a1), "r"(a2), "r"(a3), "r"(b0), "r"(b1));
}
#define FU(x) __float_as_uint(x)

// ---------------- grouped tf32x3 GEMM, register-staged double buffer --------
// Tile 64x128xK16, 256 threads, 8 warps (2m x 4n), warp tile 32x32.
// Per op: C[M,N] (+)= A[M,K] @ op(B). TB: B is NxK (C = A @ B^T).
// Ksplit>0: for k >= Ksplit the B operand switches to B2 (k rebased).
struct GOp {
    const float* A; const float* B; const float* B2; float* C;
    int K, Ksplit, lda, ldb, ldc;
    int ntiles, blkStart;
    int tb, acc;
};
struct GOps { GOp op[6]; int n; };

__global__ __launch_bounds__(256) void gg_k(GOps ops) {
    int oi = 0;
#pragma unroll
    for (int q = 1; q < 6; q++)
        if (q < ops.n && (int)blockIdx.x >= ops.op[q].blkStart) oi = q;
    const GOp o = ops.op[oi];
    const int local = blockIdx.x - o.blkStart;
    const int bm = (local / o.ntiles) * 64;
    const int bn = (local % o.ntiles) * 128;

    __shared__ float2 AsHL[16][64 + 4];
    __shared__ float2 BsHL[16][128 + 4];

    const int tid = threadIdx.x;
    const int lane = tid & 31, w = tid >> 5;
    const int wm = w & 1, wn = w >> 1;
    const int g = lane >> 2, t = lane & 3;

    // staging indices
    const int arow = tid >> 2, akq = (tid & 3) << 2;        // A: 64x16
    const int bkk = tid >> 5, bnq = (tid & 31) << 2;        // B !tb: 16x128 (2 pieces)
    const int brow = tid >> 2, bkq = (tid & 3) << 2;        // B tb: 128x16 (2 pieces)

    float4 ra, rb0, rb1;
    // prologue: load k0 = 0 (always below Ksplit)
    ra = *reinterpret_cast<const float4*>(&o.A[(size_t)(bm + arow) * o.lda + akq]);
    if (!o.tb) {
        rb0 = *reinterpret_cast<const float4*>(&o.B[(size_t)(bkk    ) * o.ldb + bn + bnq]);
        rb1 = *reinterpret_cast<const float4*>(&o.B[(size_t)(bkk + 8) * o.ldb + bn + bnq]);
    } else {
        rb0 = *reinterpret_cast<const float4*>(&o.B[(size_t)(bn + brow     ) * o.ldb + bkq]);
        rb1 = *reinterpret_cast<const float4*>(&o.B[(size_t)(bn + brow + 64) * o.ldb + bkq]);
    }

    float4 acc[2][4];
#pragma unroll
    for (int i = 0; i < 2; i++)
#pragma unroll
        for (int j = 0; j < 4; j++) acc[i][j] = make_float4(0.f, 0.f, 0.f, 0.f);

    for (int k0 = 0; k0 < o.K; k0 += 16) {
        // commit staged tile to smem
        AsHL[akq + 0][arow] = split_tf32(ra.x);
        AsHL[akq + 1][arow] = split_tf32(ra.y);
        AsHL[akq + 2][arow] = split_tf32(ra.z);
        AsHL[akq + 3][arow] = split_tf32(ra.w);
        if (!o.tb) {
            BsHL[bkk][bnq + 0] = split_tf32(rb0.x);
            BsHL[bkk][bnq + 1] = split_tf32(rb0.y);
            BsHL[bkk][bnq + 2] = split_tf32(rb0.z);
            BsHL[bkk][bnq + 3] = split_tf32(rb0.w);
            BsHL[bkk + 8][bnq + 0] = split_tf32(rb1.x);
            BsHL[bkk + 8][bnq + 1] = split_tf32(rb1.y);
            BsHL[bkk + 8][bnq + 2] = split_tf32(rb1.z);
            BsHL[bkk + 8][bnq + 3] = split_tf32(rb1.w);
        } else {
            BsHL[bkq + 0][brow] = split_tf32(rb0.x);
            BsHL[bkq + 1][brow] = split_tf32(rb0.y);
            BsHL[bkq + 2][brow] = split_tf32(rb0.z);
            BsHL[bkq + 3][brow] = split_tf32(rb0.w);
            BsHL[bkq + 0][brow + 64] = split_tf32(rb1.x);
            BsHL[bkq + 1][brow + 64] = split_tf32(rb1.y);
            BsHL[bkq + 2][brow + 64] = split_tf32(rb1.z);
            BsHL[bkq + 3][brow + 64] = split_tf32(rb1.w);
        }
        __syncthreads();
        // prefetch next tile into registers (latency overlaps MMAs below)
        const int kn = k0 + 16;
        if (kn < o.K) {
            ra = *reinterpret_cast<const float4*>(&o.A[(size_t)(bm + arow) * o.lda + kn + akq]);
            const float* Bb = o.B; int kb = kn;
            if (o.Ksplit && kn >= o.Ksplit) { Bb = o.B2; kb = kn - o.Ksplit; }
            if (!o.tb) {
                rb0 = *reinterpret_cast<const float4*>(&Bb[(size_t)(kb + bkk    ) * o.ldb + bn + bnq]);
                rb1 = *reinterpret_cast<const float4*>(&Bb[(size_t)(kb + bkk + 8) * o.ldb + bn + bnq]);
            } else {
                rb0 = *reinterpret_cast<const float4*>(&Bb[(size_t)(bn + brow     ) * o.ldb + kb + bkq]);
                rb1 = *reinterpret_cast<const float4*>(&Bb[(size_t)(bn + brow + 64) * o.ldb + kb + bkq]);
            }
        }
#pragma unroll
        for (int ks = 0; ks < 16; ks += 8) {
            float2 a[2][4], b[4][2];
#pragma unroll
            for (int i = 0; i < 2; i++) {
                int m = wm * 32 + i * 16;
                a[i][0] = AsHL[ks + t    ][m + g];
                a[i][1] = AsHL[ks + t    ][m + g + 8];
                a[i][2] = AsHL[ks + t + 4][m + g];
                a[i][3] = AsHL[ks + t + 4][m + g + 8];
            }
#pragma unroll
            for (int j = 0; j < 4; j++) {
                int nn = wn * 32 + j * 8;
                b[j][0] = BsHL[ks + t    ][nn + g];
                b[j][1] = BsHL[ks + t + 4][nn + g];
            }
#pragma unroll
            for (int i = 0; i < 2; i++)
#pragma unroll
                for (int j = 0; j < 4; j++) {
                    mma_tf32(acc[i][j], FU(a[i][0].x), FU(a[i][1].x), FU(a[i][2].x), FU(a[i][3].x),
                             FU(b[j][0].x), FU(b[j][1].x));
                    mma_tf32(acc[i][j], FU(a[i][0].x), FU(a[i][1].x), FU(a[i][2].x), FU(a[i][3].x),
                             FU(b[j][0].y), FU(b[j][1].y));
                    mma_tf32(acc[i][j], FU(a[i][0].y), FU(a[i][1].y), FU(a[i][2].y), FU(a[i][3].y),
                             FU(b[j][0].x), FU(b[j][1].x));
                }
        }
        __syncthreads();
    }
    // epilogue
#pragma unroll
    for (int i = 0; i < 2; i++) {
        int r0 = bm + wm * 32 + i * 16 + g;
        int r1 = r0 + 8;
#pragma unroll
        for (int j = 0; j < 4; j++) {
            int c = bn + wn * 32 + j * 8 + 2 * t;
            float2 v0 = make_float2(acc[i][j].x, acc[i][j].y);
            float2 v1 = make_float2(acc[i][j].z, acc[i][j].w);
            float* p0 = o.C + (size_t)r0 * o.ldc + c;
            float* p1 = o.C + (size_t)r1 * o.ldc + c;
            if (o.acc) {
                float2 u0 = *reinterpret_cast<const float2*>(p0);
                float2 u1 = *reinterpret_cast<const float2*>(p1);
                v0.x += u0.x; v0.y += u0.y; v1.x += u1.x; v1.y += u1.y;
            }
            *reinterpret_cast<float2*>(p0) = v0;
            *reinterpret_cast<float2*>(p1) = v1;
        }
    }
}

// ---------------- fused quadratic-term GEMM (tf32x3, pipelined) -------------
// Partials of diag(rvf @ M4 @ rvf^T): tile 128x128, epilogue dots each C element
// with the matching rvf value, reduces per row into g_quad8[row][bx].
__global__ __launch_bounds__(256) void k_quad(
    const float* __restrict__ A /*rvf*/, const float* __restrict__ B /*M4*/)
{
    __shared__ float2 AsHL[16][128 + 4];
    __shared__ float2 BsHL[16][128 + 4];
    __shared__ float red[128];

    const int tid = threadIdx.x;
    const int lane = tid & 31, w = tid >> 5;
    const int wm = w & 1, wn = w >> 1;
    const int g = lane >> 2, t = lane & 3;
    const int bm = blockIdx.y * 128;
    const int bn = blockIdx.x * 128;

    const int arow = tid >> 2, akq = (tid & 3) << 2;   // A pieces: rows arow, arow+64
    const int bkk = tid >> 5, bnq = (tid & 31) << 2;   // B pieces: k rows bkk, bkk+8

    float4 ra0, ra1, rb0, rb1;
    ra0 = *reinterpret_cast<const float4*>(&A[(size_t)(bm + arow     ) * DD + akq]);
    ra1 = *reinterpret_cast<const float4*>(&A[(size_t)(bm + arow + 64) * DD + akq]);
    rb0 = *reinterpret_cast<const float4*>(&B[(size_t)(bkk    ) * DD + bn + bnq]);
    rb1 = *reinterpret_cast<const float4*>(&B[(size_t)(bkk + 8) * DD + bn + bnq]);

    float4 acc[4][4];
#pragma unroll
    for (int i = 0; i < 4; i++)
#pragma unroll
        for (int j = 0; j < 4; j++) acc[i][j] = make_float4(0.f, 0.f, 0.f, 0.f);

    for (int k0 = 0; k0 < DD; k0 += 16) {
        AsHL[akq + 0][arow] = split_tf32(ra0.x);
        AsHL[akq + 1][arow] = split_tf32(ra0.y);
        AsHL[akq + 2][arow] = split_tf32(ra0.z);
        AsHL[akq + 3][arow] = split_tf32(ra0.w);
        AsHL[akq + 0][arow + 64] = split_tf32(ra1.x);
        AsHL[akq + 1][arow + 64] = split_tf32(ra1.y);
        AsHL[akq + 2][arow + 64] = split_tf32(ra1.z);
        AsHL[akq + 3][arow + 64] = split_tf32(ra1.w);
        BsHL[bkk][bnq + 0] = split_tf32(rb0.x);
        BsHL[bkk][bnq + 1] = split_tf32(rb0.y);
        BsHL[bkk][bnq + 2] = split_tf32(rb0.z);
        BsHL[bkk][bnq + 3] = split_tf32(rb0.w);
        BsHL[bkk + 8][bnq + 0] = split_tf32(rb1.x);
        BsHL[bkk + 8][bnq + 1] = split_tf32(rb1.y);
        BsHL[bkk + 8][bnq + 2] = split_tf32(rb1.z);
        BsHL[bkk + 8][bnq + 3] = split_tf32(rb1.w);
        __syncthreads();
        const int kn = k0 + 16;
        if (kn < DD) {
            ra0 = *reinterpret_cast<const float4*>(&A[(size_t)(bm + arow     ) * DD + kn + akq]);
            ra1 = *reinterpret_cast<const float4*>(&A[(size_t)(bm + arow + 64) * DD + kn + akq]);
            rb0 = *reinterpret_cast<const float4*>(&B[(size_t)(kn + bkk    ) * DD + bn + bnq]);
            rb1 = *reinterpret_cast<const float4*>(&B[(size_t)(kn + bkk + 8) * DD + bn + bnq]);
        }
#pragma unroll
        for (int ks = 0; ks < 16; ks += 8) {
            float2 a[4][4], b[4][2];
#pragma unroll
            for (int i = 0; i < 4; i++) {
                int m = wm * 64 + i * 16;
                a[i][0] = AsHL[ks + t    ][m + g];
                a[i][1] = AsHL[ks + t    ][m + g + 8];
                a[i][2] = AsHL[ks + t + 4][m + g];
                a[i][3] = AsHL[ks + t + 4][m + g + 8];
            }
#pragma unroll
            for (int j = 0; j < 4; j++) {
                int nn = wn * 32 + j * 8;
                b[j][0] = BsHL[ks + t    ][nn + g];
                b[j][1] = BsHL[ks + t + 4][nn + g];
            }
#pragma unroll
            for (int i = 0; i < 4; i++)
#pragma unroll
                for (int j = 0; j < 4; j++) {
                    mma_tf32(acc[i][j], FU(a[i][0].x), FU(a[i][1].x), FU(a[i][2].x), FU(a[i][3].x),
                             FU(b[j][0].x), FU(b[j][1].x));
                    mma_tf32(acc[i][j], FU(a[i][0].x), FU(a[i][1].x), FU(a[i][2].x), FU(a[i][3].x),
                             FU(b[j][0].y), FU(b[j][1].y));
                    mma_tf32(acc[i][j], FU(a[i][0].y), FU(a[i][1].y), FU(a[i][2].y), FU(a[i][3].y),
                             FU(b[j][0].x), FU(b[j][1].x));
                }
        }
        __syncthreads();
    }
    if (tid < 128) red[tid] = 0.f;
    __syncthreads();
#pragma unroll
    for (int i = 0; i < 4; i++) {
        int mrow = wm * 64 + i * 16 + g;
        int r0 = bm + mrow, r1 = r0 + 8;
        float p0 = 0.f, p1 = 0.f;
#pragma unroll
        for (int j = 0; j < 4; j++) {
            int c = bn + wn * 32 + j * 8 + 2 * t;
            float2 v0 = *reinterpret_cast<const float2*>(&A[(size_t)r0 * DD + c]);
            float2 v1 = *reinterpret_cast<const float2*>(&A[(size_t)r1 * DD + c]);
            p0 += acc[i][j].x * v0.x + acc[i][j].y * v0.y;
            p1 += acc[i][j].z * v1.x + acc[i][j].w * v1.y;
        }
        atomicAdd(&red[mrow], p0);
        atomicAdd(&red[mrow + 8], p1);
    }
    __syncthreads();
    if (tid < 128)
        g_quad8[(size_t)(bm + tid) * 8 + blockIdx.x] = red[tid];
}

// ---------------- small kernels ---------------------------------------------
__global__ __launch_bounds__(256) void k_init(int n) {
    int i = blockIdx.x * 256 + threadIdx.x;
    if (i < n * n) g_T[i] = 0.f;
    if (i < n) { g_Ss[i] = 0.f; g_So[i] = 0.f; g_ms[i] = 0u; g_mo[i] = 0u; g_flag[i] = 0; }
}

// a0 = b_rel@Ws_r + b_sbj ; b0 = b_rel@Wo_r + b_obj   (one kernel, 16 blocks)
__global__ __launch_bounds__(256) void k_biasvec2(const float* __restrict__ brel,
    const float* __restrict__ Wa, const float* __restrict__ ba,
    const float* __restrict__ Wb, const float* __restrict__ bb)
{
    const int which = blockIdx.x >> 3;
    const int j = ((blockIdx.x & 7) << 7) + (threadIdx.x & 127);
    const int half = threadIdx.x >> 7;
    const float* W = which ? Wb : Wa;
    float acc = 0.f;
#pragma unroll 4
    for (int k = half * 512; k < half * 512 + 512; k++)
        acc += brel[k] * W[(size_t)k * DD + j];
    __shared__ float red[256];
    red[threadIdx.x] = acc;
    __syncthreads();
    if (half == 0) {
        float v = red[threadIdx.x] + red[threadIdx.x + 128] + (which ? bb[j] : ba[j]);
        if (which) g_b0[j] = v; else g_a0[j] = v;
    }
}

// add a0 into A1 slot of CAT, b0 into B2 slot of CAT2
__global__ void k_addrow(int n) {
    int idx = blockIdx.x * blockDim.x + threadIdx.x;
    if (idx >= n * DD) return;
    int i = idx >> 10, j = idx & (DD - 1);
    g_CAT [(size_t)i * 2 * DD + j] += g_a0[j];
    g_CAT2[(size_t)i * 2 * DD + j] += g_b0[j];
}

// c[i] = dot(X[i][0:DD], X[i][DD:2*DD])  over a [n][2*DD] buffer
__global__ __launch_bounds__(256) void k_rowdot(const float* __restrict__ X, float* __restrict__ c) {
    int i = blockIdx.x;
    __shared__ float red[256];
    float acc = 0.f;
    const float* row = X + (size_t)i * 2 * DD;
    for (int j = threadIdx.x; j < DD; j += 256)
        acc += row[j] * row[DD + j];
    red[threadIdx.x] = acc; __syncthreads();
    for (int s = 128; s; s >>= 1) {
        if (threadIdx.x < s) red[threadIdx.x] += red[threadIdx.x + s];
        __syncthreads();
    }
    if (threadIdx.x == 0) c[i] = red[0];
}

__device__ __forceinline__ unsigned f2key(float x) {
    unsigned u = __float_as_uint(x);
    return u ^ ((unsigned)((int)u >> 31) | 0x80000000u);
}
__device__ __forceinline__ float key2f(unsigned k) {
    unsigned u = (k & 0x80000000u) ? (k ^ 0x80000000u) : ~k;
    return __uint_as_float(u);
}

__global__ __launch_bounds__(256) void k_logits(const float* __restrict__ rvf,
                                                const int* __restrict__ sbj, const int* __restrict__ obj,
                                                int e, int n, float inv_sqrt_d) {
    int warp = (blockIdx.x * blockDim.x + threadIdx.x) >> 5;
    int lane = threadIdx.x & 31;
    if (warp >= e) return;
    int s = sbj[warp], o = obj[warp];
    const float* r  = rvf  + (size_t)warp * DD;
    const float* ds = g_Ds + (size_t)s * DD;
    const float* dd = g_Do + (size_t)o * DD;
    float acc = 0.f;
#pragma unroll 4
    for (int j = lane; j < DD; j += 32)
        acc += r[j] * (ds[j] + dd[j]);
#pragma unroll
    for (int off = 16; off; off >>= 1) acc += __shfl_down_sync(0xffffffffu, acc, off);
    if (lane == 0) {
        float q = 0.f;
#pragma unroll
        for (int b = 0; b < 8; b++) q += g_quad8[(size_t)warp * 8 + b];
        float l = (acc + q + g_c1[s] + g_c2[o] + g_G[s * n + o]) * inv_sqrt_d;
        g_logits[warp] = l;
        g_flag[s] = 1;
        g_flag[o] = 1;
    }
}

__global__ void k_segmax(const int* __restrict__ sbj, const int* __restrict__ obj, int e) {
    int i = blockIdx.x * blockDim.x + threadIdx.x;
    if (i >= e) return;
    unsigned k = f2key(g_logits[i]);
    atomicMax(&g_ms[sbj[i]], k);
    atomicMax(&g_mo[obj[i]], k);
}

__global__ void k_expsum(const int* __restrict__ sbj, const int* __restrict__ obj, int e) {
    int i = blockIdx.x * blockDim.x + threadIdx.x;
    if (i >= e) return;
    float l = g_logits[i];
    int s = sbj[i], o = obj[i];
    float es = expf(l - key2f(g_ms[s]));
    float eo = expf(l - key2f(g_mo[o]));
    g_es[i] = es; g_eo[i] = eo;
    atomicAdd(&g_Ss[s], es);
    atomicAdd(&g_So[o], eo);
}

__global__ void k_scatterT(const int* __restrict__ sbj, const int* __restrict__ obj, int e, int n) {
    int i = blockIdx.x * blockDim.x + threadIdx.x;
    if (i >= e) return;
    int s = sbj[i], o = obj[i];
    atomicAdd(&g_T[s * n + o], g_es[i] / g_Ss[s]);
    atomicAdd(&g_T[o * n + s], g_eo[i] / g_So[o]);
}

__global__ void k_final(const float* __restrict__ visual, const float* __restrict__ bctx,
                        float* __restrict__ out, int n) {
    int idx = blockIdx.x * blockDim.x + threadIdx.x;
    if (idx >= n * DD) return;
    int i = idx >> 10;
    int j = idx & (DD - 1);
    float v = visual[idx];
    if (g_flag[i]) v += g_Uc[idx] + bctx[j];
    out[idx] = v;
}

// ---------------- host orchestration ----------------------------------------
template <typename T>
static float* symf(T& sym) { void* p = nullptr; cudaGetSymbolAddress(&p, sym); return (float*)p; }

static GOp mkop(const float* A, const float* B, const float* B2, float* C,
                int M, int N, int K, int Ksplit,
                int lda, int ldb, int ldc, bool tb, bool acc, int blkStart) {
    GOp o;
    o.A = A; o.B = B; o.B2 = B2 ? B2 : B; o.C = C;
    o.K = K; o.Ksplit = Ksplit; o.lda = lda; o.ldb = ldb; o.ldc = ldc;
    o.ntiles = N / 128; o.blkStart = blkStart;
    o.tb = tb ? 1 : 0; o.acc = acc ? 1 : 0;
    return o;
}
static int opblocks(int M, int N) { return (M / 64) * (N / 128); }

extern "C" void kernel_launch(void* const* d_in, const int* in_sizes, int n_in,
                              void* d_out, int out_size) {
    const float* visual = (const float*)d_in[0];
    const float* rvf    = (const float*)d_in[1];
    const float* W_rel  = (const float*)d_in[2];
    const float* b_rel  = (const float*)d_in[3];
    const float* W_sbj  = (const float*)d_in[4];
    const float* b_sbj  = (const float*)d_in[5];
    const float* W_obj  = (const float*)d_in[6];
    const float* b_obj  = (const float*)d_in[7];
    const float* W_ctx  = (const float*)d_in[8];
    const float* b_ctx  = (const float*)d_in[9];
    const int*   sbj    = (const int*)  d_in[10];
    const int*   obj    = (const int*)  d_in[11];

    const int n = in_sizes[0] / DD;   // 768
    const int e = in_sizes[10];       // 24576
    float* out = (float*)d_out;

    const float* Wr_s = W_rel;
    const float* Wr_o = W_rel + (size_t)DD * DD;
    const float* Wr_r = W_rel + (size_t)2 * DD * DD;
    const float* Ws_v = W_sbj;
    const float* Ws_r = W_sbj + (size_t)DD * DD;
    const float* Wo_v = W_obj;
    const float* Wo_r = W_obj + (size_t)DD * DD;

    float* P   = symf(g_P);   float* Q    = symf(g_Q);
    float* CAT = symf(g_CAT); float* CAT2 = symf(g_CAT2);
    float* A1  = CAT;         float* B1   = CAT + DD;     // ldc = 2*DD
    float* B2  = CAT2;        float* A2   = CAT2 + DD;
    float* Cs  = symf(g_Cs);  float* Co   = symf(g_Co);
    float* Ds  = symf(g_Ds);  float* Do   = symf(g_Do);
    float* Ct  = symf(g_ctx); float* Uc   = symf(g_Uc);
    float* U1  = symf(g_U1);  float* V1   = symf(g_V1);  float* M4 = symf(g_M4);
    float* G   = symf(g_G);   float* T    = symf(g_T);
    float* c1  = symf(g_c1);  float* c2   = symf(g_c2);

    k_init<<<(n * n + 255) / 256, 256>>>(n);

    // ---- L1: visual@{Wr_s,Wr_o,Ws_v,Wo_v} + weight products U1,V1
    {
        GOps ops; ops.n = 6; int bs = 0;
        ops.op[0] = mkop(visual, Wr_s, 0, P,  n, DD, DD, 0, DD, DD, DD,    false, false, bs); bs += opblocks(n, DD);
        ops.op[1] = mkop(visual, Wr_o, 0, Q,  n, DD, DD, 0, DD, DD, DD,    false, false, bs); bs += opblocks(n, DD);
        ops.op[2] = mkop(visual, Ws_v, 0, A1, n, DD, DD, 0, DD, DD, 2*DD,  false, false, bs); bs += opblocks(n, DD);
        ops.op[3] = mkop(visual, Wo_v, 0, B2, n, DD, DD, 0, DD, DD, 2*DD,  false, false, bs); bs += opblocks(n, DD);
        ops.op[4] = mkop(Wr_r,   Ws_r, 0, U1, DD, DD, DD, 0, DD, DD, DD,   false, false, bs); bs += opblocks(DD, DD);
        ops.op[5] = mkop(Wr_r,   Wo_r, 0, V1, DD, DD, DD, 0, DD, DD, DD,   false, false, bs); bs += opblocks(DD, DD);
        gg_k<<<bs, 256>>>(ops);
    }
    // ---- L2: A1+=P@Ws_r, A2=Q@Ws_r, B1=P@Wo_r, B2+=Q@Wo_r, M4=U1@V1^T
    {
        GOps ops; ops.n = 5; int bs = 0;
        ops.op[0] = mkop(P, Ws_r, 0, A1, n, DD, DD, 0, DD, DD, 2*DD, false, true,  bs); bs += opblocks(n, DD);
        ops.op[1] = mkop(Q, Ws_r, 0, A2, n, DD, DD, 0, DD, DD, 2*DD, false, false, bs); bs += opblocks(n, DD);
        ops.op[2] = mkop(P, Wo_r, 0, B1, n, DD, DD, 0, DD, DD, 2*DD, false, false, bs); bs += opblocks(n, DD);
        ops.op[3] = mkop(Q, Wo_r, 0, B2, n, DD, DD, 0, DD, DD, 2*DD, false, true,  bs); bs += opblocks(n, DD);
        ops.op[4] = mkop(U1, V1,  0, M4, DD, DD, DD, 0, DD, DD, DD,  true,  false, bs); bs += opblocks(DD, DD);
        gg_k<<<bs, 256>>>(ops);
    }
    // ---- bias folds + per-node dots
    k_biasvec2<<<16, 256>>>(b_rel, Ws_r, b_sbj, Wo_r, b_obj);
    k_addrow<<<(n * DD + 255) / 256, 256>>>(n);
    k_rowdot<<<n, 256>>>(CAT,  c1);   // dot(A1, B1)
    k_rowdot<<<n, 256>>>(CAT2, c2);   // dot(B2, A2)

    // ---- quadratic term (E-scale, fused)
    {
        dim3 g(8, e / 128);
        k_quad<<<g, 256>>>(rvf, M4);
    }
    // ---- L3: Cs, Co (K=2048 concat), G = CAT @ CAT2^T
    {
        GOps ops; ops.n = 3; int bs = 0;
        ops.op[0] = mkop(CAT,  Wo_r, Ws_r, Cs, n, DD, 2*DD, DD, 2*DD, DD,   DD,  true, false, bs); bs += opblocks(n, DD);
        ops.op[1] = mkop(CAT2, Ws_r, Wo_r, Co, n, DD, 2*DD, DD, 2*DD, DD,   DD,  true, false, bs); bs += opblocks(n, DD);
        ops.op[2] = mkop(CAT,  CAT2, 0,    G,  n, n,  2*DD, 0,  2*DD, 2*DD, n,   true, false, bs); bs += opblocks(n, n);
        gg_k<<<bs, 256>>>(ops);
    }
    // ---- L4: Ds = Cs@Wr_r^T, Do = Co@Wr_r^T
    {
        GOps ops; ops.n = 2; int bs = 0;
        ops.op[0] = mkop(Cs, Wr_r, 0, Ds, n, DD, DD, 0, DD, DD, DD, true, false, bs); bs += opblocks(n, DD);
        ops.op[1] = mkop(Co, Wr_r, 0, Do, n, DD, DD, 0, DD, DD, DD, true, false, bs); bs += opblocks(n, DD);
        gg_k<<<bs, 256>>>(ops);
    }
    // ---- edge logits + softmax + attention matrix
    float inv_sqrt_d = 1.0f / sqrtf((float)DD);
    k_logits  <<<(e * 32 + 255) / 256, 256>>>(rvf, sbj, obj, e, n, inv_sqrt_d);
    k_segmax  <<<(e + 255) / 256, 256>>>(sbj, obj, e);
    k_expsum  <<<(e + 255) / 256, 256>>>(sbj, obj, e);
    k_scatterT<<<(e + 255) / 256, 256>>>(sbj, obj, e, n);

    // ---- ctx = T @ visual ; U = ctx @ W_ctx
    {
        GOps ops; ops.n = 1;
        ops.op[0] = mkop(T, visual, 0, Ct, n, DD, n, 0, n, DD, DD, false, false, 0);
        gg_k<<<opblocks(n, DD), 256>>>(ops);
    }
    {
        GOps ops; ops.n = 1;
        ops.op[0] = mkop(Ct, W_ctx, 0, Uc, n, DD, DD, 0, DD, DD, DD, false, false, 0);
        gg_k<<<opblocks(n, DD), 256>>>(ops);
    }

    size_t vj_off = 0;
    if ((size_t)out_size == (size_t)e * DD + (size_t)n * DD) {
        vj_off = (size_t)e * DD;
        cudaMemcpyAsync(out, rvf, (size_t)e * DD * sizeof(float),
                        cudaMemcpyDeviceToDevice, 0);
    }
    k_final<<<(n * DD + 255) / 256, 256>>>(visual, b_ctx, out + vj_off, n);
}